// round 2
// baseline (speedup 1.0000x reference)
#include <cuda_runtime.h>
#include <math.h>

#define B_    8
#define TS    2
#define SEQ   720
#define ENC   862
#define MARKD 4
#define NTOK  866
#define D     256
#define NH    8
#define EH    32
#define DFF   512
#define DB    720
#define LAYERS 2
#define EPS   1e-5f
#define MROWS (B_*NTOK)   // 6928

// ---------------- scratch (device globals; no allocation) ----------------
__device__ float g_xin [(size_t)MROWS*SEQ];
__device__ float g_mean[B_*ENC];
__device__ float g_std [B_*ENC];
__device__ float g_h   [(size_t)MROWS*D];
__device__ float g_qkv [(size_t)3*MROWS*D];
__device__ float g_att [(size_t)MROWS*D];
__device__ float g_xatt[(size_t)MROWS*D];
__device__ float g_xln [(size_t)MROWS*D];
__device__ float g_y1  [(size_t)MROWS*DFF];
__device__ float g_y   [(size_t)MROWS*D];
__device__ float g_xs  [(size_t)MROWS*D];
__device__ float g_hh  [(size_t)MROWS*D];
__device__ float g_cat [(size_t)MROWS*2*D];
__device__ float g_o56 [(size_t)2*MROWS*DB];
__device__ float g_out [(size_t)MROWS*DB];
__device__ float g_scores[(size_t)B_*NH*NTOK*NTOK];   // 192 MB

// ---------------- f32x2 helpers (sm_103a packed fp32) ----------------
__device__ __forceinline__ unsigned long long ffma2(unsigned long long a,
                                                    unsigned long long b,
                                                    unsigned long long c){
    unsigned long long d;
    asm("fma.rn.f32x2 %0, %1, %2, %3;" : "=l"(d) : "l"(a), "l"(b), "l"(c));
    return d;
}
__device__ __forceinline__ unsigned long long packdup(float x){
    unsigned long long d;
    asm("mov.b64 %0, {%1, %1};" : "=l"(d) : "f"(x));
    return d;
}
__device__ __forceinline__ float2 unpack2(unsigned long long v){
    float lo, hi;
    asm("mov.b64 {%0, %1}, %2;" : "=f"(lo), "=f"(hi) : "l"(v));
    return make_float2(lo, hi);
}

// ---------------- reductions ----------------
__device__ __forceinline__ float blockReduce(float v, bool domax){
    __shared__ float sh[33];
    int lane = threadIdx.x & 31, wid = threadIdx.x >> 5;
    __syncthreads();
    #pragma unroll
    for (int o = 16; o; o >>= 1){
        float ov = __shfl_down_sync(0xffffffffu, v, o);
        v = domax ? fmaxf(v, ov) : (v + ov);
    }
    if (lane == 0) sh[wid] = v;
    __syncthreads();
    if (wid == 0){
        int nw = blockDim.x >> 5;
        v = (lane < nw) ? sh[lane] : (domax ? -1e30f : 0.f);
        #pragma unroll
        for (int o = 16; o; o >>= 1){
            float ov = __shfl_down_sync(0xffffffffu, v, o);
            v = domax ? fmaxf(v, ov) : (v + ov);
        }
        if (lane == 0) sh[32] = v;
    }
    __syncthreads();
    return sh[32];
}

// ---------------- input standardization stats ----------------
__global__ void stats_kernel(const float* __restrict__ mbx, int t){
    int b = blockIdx.y;
    int n = blockIdx.x * blockDim.x + threadIdx.x;
    if (n >= ENC) return;
    const float* base = mbx + ((size_t)(b*TS + t)*SEQ)*ENC + n;
    float s = 0.f, ss = 0.f;
    for (int i = 0; i < SEQ; i++){
        float v = base[(size_t)i*ENC];
        s += v; ss += v*v;
    }
    float m = s * (1.f/SEQ);
    float var = ss * (1.f/SEQ) - m*m;
    g_mean[b*ENC + n] = m;
    g_std [b*ENC + n] = sqrtf(var + EPS);
}

// ---------------- build xin [B, NTOK, SEQ] ----------------
__global__ void xin_kernel(const float* __restrict__ mbx,
                           const float* __restrict__ mbxm, int t){
    size_t total = (size_t)B_*NTOK*SEQ;
    size_t idx = (size_t)blockIdx.x*blockDim.x + threadIdx.x;
    if (idx >= total) return;
    int s = (int)(idx % SEQ);
    size_t r = idx / SEQ;
    int n = (int)(r % NTOK);
    int b = (int)(r / NTOK);
    float v;
    if (n < ENC){
        v = mbx[((size_t)(b*TS + t)*SEQ + s)*ENC + n];
        v = (v - g_mean[b*ENC + n]) / g_std[b*ENC + n];
    } else {
        v = mbxm[((size_t)(b*TS + t)*SEQ + s)*MARKD + (n - ENC)];
    }
    g_xin[idx] = v;
}

// ---------------- GEMM: C = A @ W^T + bias (FFMA2, double-buffered) ------
struct GemmArgs {
    const float* A[3];
    const float* W[3];
    const float* Bv[3];
    float*       C[3];
};

template<int TM, int TN, int ACT>
__global__ __launch_bounds__(256)
void gemm2_kernel(GemmArgs p, int M, int N, int K,
                  int tilesM, int tilesN, int nTiles){
    constexpr int AV  = TM/64;      // float4 loads per thread for A tile
    constexpr int BV  = TN/64;
    constexpr int TMR = TM/16;      // rows per thread
    constexpr int TNR = TN/16;      // cols per thread

    __shared__ __align__(16) float              As[2][16][TM];
    __shared__ __align__(16) unsigned long long Bs[2][16][TN]; // (b,b) dup

    const int tid   = threadIdx.x;
    const int ldRow = tid >> 2;        // 0..63
    const int ldCol = (tid & 3) * 4;   // 0,4,8,12
    const int tr = tid >> 4, tc = tid & 15;
    const int tpz = tilesM * tilesN;

    for (int t = blockIdx.x; t < nTiles; t += gridDim.x){
        const int z  = t / tpz;
        const int r  = t - z*tpz;
        const int bm = (r / tilesN) * TM;
        const int bn = (r % tilesN) * TN;
        const float* __restrict__ A    = p.A[z];
        const float* __restrict__ W    = p.W[z];
        const float* __restrict__ bias = p.Bv[z];
        float*       __restrict__ C    = p.C[z];

        unsigned long long acc[TMR/2][TNR];
        #pragma unroll
        for (int i = 0; i < TMR/2; i++)
            #pragma unroll
            for (int j = 0; j < TNR; j++) acc[i][j] = 0ull;

        float4 Areg[AV], Breg[BV];
        // prologue: load k-tile 0
        #pragma unroll
        for (int v = 0; v < AV; v++){
            int gm = bm + ldRow + 64*v;
            Areg[v] = (gm < M) ? *(const float4*)(A + (size_t)gm*K + ldCol)
                               : make_float4(0.f,0.f,0.f,0.f);
        }
        #pragma unroll
        for (int v = 0; v < BV; v++){
            int gn = bn + ldRow + 64*v;
            Breg[v] = (gn < N) ? *(const float4*)(W + (size_t)gn*K + ldCol)
                               : make_float4(0.f,0.f,0.f,0.f);
        }
        #pragma unroll
        for (int v = 0; v < AV; v++){
            int row = ldRow + 64*v;
            As[0][ldCol+0][row] = Areg[v].x; As[0][ldCol+1][row] = Areg[v].y;
            As[0][ldCol+2][row] = Areg[v].z; As[0][ldCol+3][row] = Areg[v].w;
        }
        #pragma unroll
        for (int v = 0; v < BV; v++){
            int row = ldRow + 64*v;
            Bs[0][ldCol+0][row] = packdup(Breg[v].x);
            Bs[0][ldCol+1][row] = packdup(Breg[v].y);
            Bs[0][ldCol+2][row] = packdup(Breg[v].z);
            Bs[0][ldCol+3][row] = packdup(Breg[v].w);
        }
        __syncthreads();

        const int KT = K >> 4;
        int buf = 0;
        for (int kt = 0; kt < KT; kt++){
            if (kt + 1 < KT){
                const int k0 = (kt+1) << 4;
                #pragma unroll
                for (int v = 0; v < AV; v++){
                    int gm = bm + ldRow + 64*v;
                    Areg[v] = (gm < M) ? *(const float4*)(A + (size_t)gm*K + k0 + ldCol)
                                       : make_float4(0.f,0.f,0.f,0.f);
                }
                #pragma unroll
                for (int v = 0; v < BV; v++){
                    int gn = bn + ldRow + 64*v;
                    Breg[v] = (gn < N) ? *(const float4*)(W + (size_t)gn*K + k0 + ldCol)
                                       : make_float4(0.f,0.f,0.f,0.f);
                }
            }
            #pragma unroll
            for (int kk = 0; kk < 16; kk++){
                const ulonglong2* pa = reinterpret_cast<const ulonglong2*>(&As[buf][kk][tr*TMR]);
                const ulonglong2* pb = reinterpret_cast<const ulonglong2*>(&Bs[buf][kk][tc*TNR]);
                unsigned long long ar[TMR/2], br[TNR];
                #pragma unroll
                for (int v = 0; v < TMR/4; v++){
                    ulonglong2 q = pa[v];
                    ar[2*v] = q.x; ar[2*v+1] = q.y;
                }
                #pragma unroll
                for (int v = 0; v < TNR/2; v++){
                    ulonglong2 q = pb[v];
                    br[2*v] = q.x; br[2*v+1] = q.y;
                }
                #pragma unroll
                for (int i = 0; i < TMR/2; i++)
                    #pragma unroll
                    for (int j = 0; j < TNR; j++)
                        acc[i][j] = ffma2(ar[i], br[j], acc[i][j]);
            }
            if (kt + 1 < KT){
                int nb = buf ^ 1;
                #pragma unroll
                for (int v = 0; v < AV; v++){
                    int row = ldRow + 64*v;
                    As[nb][ldCol+0][row] = Areg[v].x; As[nb][ldCol+1][row] = Areg[v].y;
                    As[nb][ldCol+2][row] = Areg[v].z; As[nb][ldCol+3][row] = Areg[v].w;
                }
                #pragma unroll
                for (int v = 0; v < BV; v++){
                    int row = ldRow + 64*v;
                    Bs[nb][ldCol+0][row] = packdup(Breg[v].x);
                    Bs[nb][ldCol+1][row] = packdup(Breg[v].y);
                    Bs[nb][ldCol+2][row] = packdup(Breg[v].z);
                    Bs[nb][ldCol+3][row] = packdup(Breg[v].w);
                }
                __syncthreads();
                buf ^= 1;
            }
        }

        #pragma unroll
        for (int i = 0; i < TMR/2; i++){
            int gm0 = bm + tr*TMR + 2*i;
            #pragma unroll
            for (int j = 0; j < TNR; j++){
                int col = bn + tc*TNR + j;
                if (col >= N) continue;
                float2 v = unpack2(acc[i][j]);
                float bs = bias[col];
                float c0 = v.x + bs, c1 = v.y + bs;
                if (ACT == 1){
                    c0 = 0.5f*c0*(1.f + erff(c0*0.70710678118654752f));
                    c1 = 0.5f*c1*(1.f + erff(c1*0.70710678118654752f));
                }
                if (gm0     < M) C[(size_t)gm0    *N + col] = c0;
                if (gm0 + 1 < M) C[(size_t)(gm0+1)*N + col] = c1;
            }
        }
        __syncthreads();
    }
}

// ---------------- attention: scores = scale * Q K^T (f32x2 k-packing) ----
__global__ __launch_bounds__(256) void scores_kernel(){
    const int bh = blockIdx.z;
    const int b = bh >> 3, h = bh & 7;
    const int i0 = blockIdx.y * 64, j0 = blockIdx.x * 64;
    __shared__ __align__(16) float Qs[64][36];
    __shared__ __align__(16) float Ks[64][36];
    const float* q = g_qkv + ((size_t)b*NTOK)*D + h*EH;
    const float* k = g_qkv + (size_t)MROWS*D + ((size_t)b*NTOK)*D + h*EH;

    for (int idx = threadIdx.x; idx < 64*32; idx += 256){
        int r = idx >> 5, e = idx & 31;
        int gi = i0 + r, gj = j0 + r;
        Qs[r][e] = (gi < NTOK) ? q[(size_t)gi*D + e] : 0.f;
        Ks[r][e] = (gj < NTOK) ? k[(size_t)gj*D + e] : 0.f;
    }
    __syncthreads();

    const int tr = threadIdx.x & 15, tc = threadIdx.x >> 4;
    unsigned long long acc[4][4];
    #pragma unroll
    for (int i = 0; i < 4; i++)
        #pragma unroll
        for (int j = 0; j < 4; j++) acc[i][j] = 0ull;

    #pragma unroll
    for (int ee = 0; ee < 32; ee += 4){
        ulonglong2 qa[4], kb[4];
        #pragma unroll
        for (int i = 0; i < 4; i++)
            qa[i] = *reinterpret_cast<const ulonglong2*>(&Qs[tr + 16*i][ee]);
        #pragma unroll
        for (int j = 0; j < 4; j++)
            kb[j] = *reinterpret_cast<const ulonglong2*>(&Ks[tc*4 + j][ee]);
        #pragma unroll
        for (int i = 0; i < 4; i++)
            #pragma unroll
            for (int j = 0; j < 4; j++){
                acc[i][j] = ffma2(qa[i].x, kb[j].x, acc[i][j]);
                acc[i][j] = ffma2(qa[i].y, kb[j].y, acc[i][j]);
            }
    }

    float* S = g_scores + (size_t)bh*NTOK*NTOK;
    const float scale = 0.17677669529663688f;  // 1/sqrt(32)
    #pragma unroll
    for (int i = 0; i < 4; i++){
        int gi = i0 + tr + 16*i;
        if (gi >= NTOK) continue;
        #pragma unroll
        for (int j = 0; j < 4; j++){
            int gj = j0 + tc*4 + j;
            if (gj < NTOK){
                float2 v = unpack2(acc[i][j]);
                S[(size_t)gi*NTOK + gj] = (v.x + v.y)*scale;
            }
        }
    }
}

// ---------------- softmax over last dim (rows of 866) ----------------
__global__ __launch_bounds__(128) void softmax_kernel(){
    size_t row = blockIdx.x;
    float* p = g_scores + row*(size_t)NTOK;
    float v[7];
    float mx = -1e30f;
    #pragma unroll
    for (int i = 0; i < 7; i++){
        int j = threadIdx.x + i*128;
        v[i] = (j < NTOK) ? p[j] : -1e30f;
        mx = fmaxf(mx, v[i]);
    }
    mx = blockReduce(mx, true);
    float sum = 0.f;
    #pragma unroll
    for (int i = 0; i < 7; i++){
        v[i] = expf(v[i] - mx);
        sum += v[i];
    }
    sum = blockReduce(sum, false);
    float inv = 1.f / sum;
    #pragma unroll
    for (int i = 0; i < 7; i++){
        int j = threadIdx.x + i*128;
        if (j < NTOK) p[j] = v[i]*inv;
    }
}

// ---------------- att = P @ V (f32x2 j-packing) ----------------
__global__ __launch_bounds__(256) void av_kernel(){
    const int bh = blockIdx.y;
    const int b = bh >> 3, h = bh & 7;
    const int i0 = blockIdx.x * 64;
    __shared__ __align__(16) float Ps [64][68];
    __shared__ __align__(16) float VsT[32][68];
    const float* S = g_scores + (size_t)bh*NTOK*NTOK;
    const float* v = g_qkv + 2*(size_t)MROWS*D + ((size_t)b*NTOK)*D + h*EH;
    const int tr = threadIdx.x & 15, tc = threadIdx.x >> 4;

    unsigned long long acc[4][2];
    #pragma unroll
    for (int i = 0; i < 4; i++){ acc[i][0] = 0ull; acc[i][1] = 0ull; }

    for (int j0 = 0; j0 < NTOK; j0 += 64){
        __syncthreads();
        for (int idx = threadIdx.x; idx < 64*64; idx += 256){
            int li = idx >> 6, lj = idx & 63;
            int gi = i0 + li, gj = j0 + lj;
            Ps[li][lj] = (gi < NTOK && gj < NTOK) ? S[(size_t)gi*NTOK + gj] : 0.f;
        }
        for (int idx = threadIdx.x; idx < 64*32; idx += 256){
            int lj = idx >> 5, e = idx & 31;
            int gj = j0 + lj;
            VsT[e][lj] = (gj < NTOK) ? v[(size_t)gj*D + e] : 0.f;
        }
        __syncthreads();
        #pragma unroll
        for (int jj = 0; jj < 64; jj += 4){
            ulonglong2 pa[4], vb[2];
            #pragma unroll
            for (int i = 0; i < 4; i++)
                pa[i] = *reinterpret_cast<const ulonglong2*>(&Ps[tr + 16*i][jj]);
            #pragma unroll
            for (int c = 0; c < 2; c++)
                vb[c] = *reinterpret_cast<const ulonglong2*>(&VsT[tc*2 + c][jj]);
            #pragma unroll
            for (int i = 0; i < 4; i++)
                #pragma unroll
                for (int c = 0; c < 2; c++){
                    acc[i][c] = ffma2(pa[i].x, vb[c].x, acc[i][c]);
                    acc[i][c] = ffma2(pa[i].y, vb[c].y, acc[i][c]);
                }
        }
    }
    #pragma unroll
    for (int i = 0; i < 4; i++){
        int gi = i0 + tr + 16*i;
        if (gi >= NTOK) continue;
        #pragma unroll
        for (int c = 0; c < 2; c++){
            float2 u = unpack2(acc[i][c]);
            g_att[((size_t)b*NTOK + gi)*D + h*EH + tc*2 + c] = u.x + u.y;
        }
    }
}

// ---------------- LayerNorm(x [- sub]) over D=256 ----------------
__global__ __launch_bounds__(256) void ln_kernel(const float* __restrict__ X,
                                                 const float* __restrict__ Sub,
                                                 const float* __restrict__ g,
                                                 const float* __restrict__ beta,
                                                 float* __restrict__ Out){
    int row = blockIdx.x, d = threadIdx.x;
    size_t i = (size_t)row*D + d;
    float v = X[i] - (Sub ? Sub[i] : 0.f);
    float mean = blockReduce(v, false) * (1.f/D);
    float dv = v - mean;
    float var = blockReduce(dv*dv, false) * (1.f/D);
    Out[i] = dv * rsqrtf(var + EPS) * g[d] + beta[d];
}

// ---------------- elementwise fusion kernels ----------------
__global__ void sub_kernel(const float* __restrict__ a, const float* __restrict__ b,
                           float* __restrict__ c, size_t n){
    size_t i = (size_t)blockIdx.x*blockDim.x + threadIdx.x;
    if (i < n) c[i] = a[i] - b[i];
}

__global__ void glu_kernel(const float* __restrict__ a, const float* __restrict__ b,
                           float* __restrict__ c, size_t n){
    size_t i = (size_t)blockIdx.x*blockDim.x + threadIdx.x;
    if (i < n) c[i] = (1.f/(1.f + expf(-a[i]))) * b[i];
}

__global__ void cat_kernel(const float* __restrict__ xatt, const float* __restrict__ y){
    size_t n = (size_t)MROWS*2*D;
    size_t i = (size_t)blockIdx.x*blockDim.x + threadIdx.x;
    if (i >= n) return;
    int c = (int)(i % (2*D));
    size_t r = i / (2*D);
    g_cat[i] = (c < D) ? xatt[r*D + c] : y[r*D + c - D];
}

__global__ void outcomb_kernel(int l){
    size_t n = (size_t)MROWS*DB;
    size_t i = (size_t)blockIdx.x*blockDim.x + threadIdx.x;
    if (i >= n) return;
    float a = g_o56[i], b = g_o56[n + i];
    float v = (1.f/(1.f + expf(-a))) * b;
    g_out[i] = l ? (v - g_out[i]) : v;
}

// ---------------- final: de-standardize, transpose, 2-scale mean ----------
__global__ void final_kernel(float* __restrict__ out, int t){
    size_t total = (size_t)B_*DB*ENC;
    size_t idx = (size_t)blockIdx.x*blockDim.x + threadIdx.x;
    if (idx >= total) return;
    int n = (int)(idx % ENC);
    size_t r = idx / ENC;
    int p = (int)(r % DB);
    int b = (int)(r / DB);
    float v = g_out[((size_t)b*NTOK + n)*DB + p] * g_std[b*ENC + n] + g_mean[b*ENC + n];
    v *= 0.5f;
    if (t == 0) out[idx] = v; else out[idx] += v;
}

// ---------------- host ----------------
static inline GemmArgs ga1(const float* A, const float* W, const float* b, float* C){
    GemmArgs g = {};
    g.A[0] = A; g.W[0] = W; g.Bv[0] = b; g.C[0] = C;
    return g;
}
static inline int gsz(int nt){ return nt < 592 ? nt : 592; }

extern "C" void kernel_launch(void* const* d_in, const int* in_sizes, int n_in,
                              void* d_out, int out_size){
    const float* mbx  = (const float*)d_in[0];
    const float* mbxm = (const float*)d_in[1];
    const float* embW = (const float*)d_in[4];
    const float* embB = (const float*)d_in[5];
    const float* Wq = (const float*)d_in[6];
    const float* Wk = (const float*)d_in[7];
    const float* Wv = (const float*)d_in[8];
    const float* Wo = (const float*)d_in[9];
    const float* W3 = (const float*)d_in[10];
    const float* W4 = (const float*)d_in[11];
    const float* bq = (const float*)d_in[12];
    const float* bk = (const float*)d_in[13];
    const float* bv = (const float*)d_in[14];
    const float* bo = (const float*)d_in[15];
    const float* b3 = (const float*)d_in[16];
    const float* b4 = (const float*)d_in[17];
    const float* W1 = (const float*)d_in[18];
    const float* b1 = (const float*)d_in[19];
    const float* W2 = (const float*)d_in[20];
    const float* b2 = (const float*)d_in[21];
    const float* W5 = (const float*)d_in[22];
    const float* b5 = (const float*)d_in[23];
    const float* W6 = (const float*)d_in[24];
    const float* b6 = (const float*)d_in[25];
    const float* ln1g = (const float*)d_in[26];
    const float* ln1b = (const float*)d_in[27];
    const float* ln2g = (const float*)d_in[28];
    const float* ln2b = (const float*)d_in[29];
    float* out = (float*)d_out;

    float *xin, *h, *qkv, *att, *xatt, *xln, *y1, *y, *xs, *hh, *cat, *o56;
    cudaGetSymbolAddress((void**)&xin,  g_xin);
    cudaGetSymbolAddress((void**)&h,    g_h);
    cudaGetSymbolAddress((void**)&qkv,  g_qkv);
    cudaGetSymbolAddress((void**)&att,  g_att);
    cudaGetSymbolAddress((void**)&xatt, g_xatt);
    cudaGetSymbolAddress((void**)&xln,  g_xln);
    cudaGetSymbolAddress((void**)&y1,   g_y1);
    cudaGetSymbolAddress((void**)&y,    g_y);
    cudaGetSymbolAddress((void**)&xs,   g_xs);
    cudaGetSymbolAddress((void**)&hh,   g_hh);
    cudaGetSymbolAddress((void**)&cat,  g_cat);
    cudaGetSymbolAddress((void**)&o56,  g_o56);

    const size_t MD = (size_t)MROWS*D;
    const int tm128 = 55;   // ceil(6928/128)
    const int tm64  = 109;  // ceil(6928/64)

    for (int t = 0; t < TS; t++){
        stats_kernel<<<dim3((ENC + 255)/256, B_), 256>>>(mbx, t);
        {
            size_t n = (size_t)B_*NTOK*SEQ;
            xin_kernel<<<(unsigned)((n + 255)/256), 256>>>(mbx, mbxm, t);
        }
        // embed: M=6928, N=256, K=720
        gemm2_kernel<64,64,0><<<gsz(tm64*4), 256>>>(
            ga1(xin, embW, embB, h), MROWS, D, SEQ, tm64, 4, tm64*4);

        for (int l = 0; l < LAYERS; l++){
            // Q, K, V in one launch
            GemmArgs q3 = {};
            q3.A[0] = h; q3.A[1] = h; q3.A[2] = h;
            q3.W[0] = Wq + (size_t)l*D*D; q3.W[1] = Wk + (size_t)l*D*D; q3.W[2] = Wv + (size_t)l*D*D;
            q3.Bv[0] = bq + l*D; q3.Bv[1] = bk + l*D; q3.Bv[2] = bv + l*D;
            q3.C[0] = qkv; q3.C[1] = qkv + MD; q3.C[2] = qkv + 2*MD;
            gemm2_kernel<128,64,0><<<gsz(tm128*4*3), 256>>>(q3, MROWS, D, D,
                                                            tm128, 4, tm128*4*3);

            scores_kernel<<<dim3(14, 14, B_*NH), 256>>>();
            softmax_kernel<<<B_*NH*NTOK, 128>>>();
            av_kernel<<<dim3(14, B_*NH), 256>>>();

            gemm2_kernel<64,64,0><<<gsz(tm64*4), 256>>>(
                ga1(att, Wo + (size_t)l*D*D, bo + l*D, xatt), MROWS, D, D,
                tm64, 4, tm64*4);

            ln_kernel<<<MROWS, 256>>>(h, xatt, ln1g + l*D, ln1b + l*D, xln);

            gemm2_kernel<128,64,1><<<gsz(tm128*8), 256>>>(
                ga1(xln, W1 + (size_t)l*DFF*D, b1 + l*DFF, y1), MROWS, DFF, D,
                tm128, 8, tm128*8);
            gemm2_kernel<64,64,0><<<gsz(tm64*4), 256>>>(
                ga1(y1, W2 + (size_t)l*D*DFF, b2 + l*D, y), MROWS, D, DFF,
                tm64, 4, tm64*4);

            sub_kernel<<<(unsigned)((MD + 255)/256), 256>>>(xln, y, xs, MD);

            GemmArgs g34 = {};
            g34.A[0] = xs; g34.A[1] = xs;
            g34.W[0] = W3 + (size_t)l*D*D; g34.W[1] = W4 + (size_t)l*D*D;
            g34.Bv[0] = b3 + l*D; g34.Bv[1] = b4 + l*D;
            g34.C[0] = qkv; g34.C[1] = qkv + MD;   // reuse q/k slots
            gemm2_kernel<128,64,0><<<gsz(tm128*4*2), 256>>>(g34, MROWS, D, D,
                                                            tm128, 4, tm128*4*2);

            glu_kernel<<<(unsigned)((MD + 255)/256), 256>>>(qkv, qkv + MD, hh, MD);
            cat_kernel<<<(unsigned)(((size_t)MROWS*2*D + 255)/256), 256>>>(xatt, y);

            GemmArgs g56 = {};
            g56.A[0] = cat; g56.A[1] = cat;
            g56.W[0] = W5 + (size_t)l*DB*2*D; g56.W[1] = W6 + (size_t)l*DB*2*D;
            g56.Bv[0] = b5 + l*DB; g56.Bv[1] = b6 + l*DB;
            g56.C[0] = o56; g56.C[1] = o56 + (size_t)MROWS*DB;
            gemm2_kernel<128,64,0><<<gsz(tm128*12*2), 256>>>(g56, MROWS, DB, 2*D,
                                                             tm128, 12, tm128*12*2);

            outcomb_kernel<<<(unsigned)(((size_t)MROWS*DB + 255)/256), 256>>>(l);

            ln_kernel<<<MROWS, 256>>>(hh, (const float*)nullptr, ln2g + l*D, ln2b + l*D, h);
        }

        final_kernel<<<(unsigned)(((size_t)B_*DB*ENC + 255)/256), 256>>>(out, t);
    }
}

// round 3
// speedup vs baseline: 1.0002x; 1.0002x over previous
#include <cuda_runtime.h>
#include <math.h>

#define B_    8
#define TS    2
#define SEQ   720
#define ENC   862
#define MARKD 4
#define NTOK  866
#define D     256
#define NH    8
#define EH    32
#define DFF   512
#define DB    720
#define LAYERS 2
#define EPS   1e-5f
#define MROWS (B_*NTOK)   // 6928

// ---------------- scratch (device globals; no allocation) ----------------
__device__ float g_xin [(size_t)MROWS*SEQ];
__device__ float g_mean[B_*ENC];
__device__ float g_std [B_*ENC];
__device__ float g_h   [(size_t)MROWS*D];
__device__ float g_qkv [(size_t)3*MROWS*D];
__device__ float g_att [(size_t)MROWS*D];
__device__ float g_xatt[(size_t)MROWS*D];
__device__ float g_xln [(size_t)MROWS*D];
__device__ float g_y1  [(size_t)MROWS*DFF];
__device__ float g_y   [(size_t)MROWS*D];
__device__ float g_xs  [(size_t)MROWS*D];
__device__ float g_hh  [(size_t)MROWS*D];
__device__ float g_cat [(size_t)MROWS*2*D];
__device__ float g_o56 [(size_t)2*MROWS*DB];
__device__ float g_out [(size_t)MROWS*DB];
__device__ float g_scores[(size_t)B_*NH*NTOK*NTOK];   // 192 MB

// ---------------- f32x2 helpers (sm_103a packed fp32) ----------------
__device__ __forceinline__ unsigned long long ffma2(unsigned long long a,
                                                    unsigned long long b,
                                                    unsigned long long c){
    unsigned long long d;
    asm("fma.rn.f32x2 %0, %1, %2, %3;" : "=l"(d) : "l"(a), "l"(b), "l"(c));
    return d;
}
__device__ __forceinline__ unsigned long long packdup(float x){
    unsigned long long d;
    asm("mov.b64 %0, {%1, %1};" : "=l"(d) : "f"(x));
    return d;
}
__device__ __forceinline__ float2 unpack2(unsigned long long v){
    float lo, hi;
    asm("mov.b64 {%0, %1}, %2;" : "=f"(lo), "=f"(hi) : "l"(v));
    return make_float2(lo, hi);
}

// ---------------- reductions ----------------
__device__ __forceinline__ float blockReduce(float v, bool domax){
    __shared__ float sh[33];
    int lane = threadIdx.x & 31, wid = threadIdx.x >> 5;
    __syncthreads();
    #pragma unroll
    for (int o = 16; o; o >>= 1){
        float ov = __shfl_down_sync(0xffffffffu, v, o);
        v = domax ? fmaxf(v, ov) : (v + ov);
    }
    if (lane == 0) sh[wid] = v;
    __syncthreads();
    if (wid == 0){
        int nw = blockDim.x >> 5;
        v = (lane < nw) ? sh[lane] : (domax ? -1e30f : 0.f);
        #pragma unroll
        for (int o = 16; o; o >>= 1){
            float ov = __shfl_down_sync(0xffffffffu, v, o);
            v = domax ? fmaxf(v, ov) : (v + ov);
        }
        if (lane == 0) sh[32] = v;
    }
    __syncthreads();
    return sh[32];
}

// ---------------- input standardization stats ----------------
__global__ void stats_kernel(const float* __restrict__ mbx, int t){
    int b = blockIdx.y;
    int n = blockIdx.x * blockDim.x + threadIdx.x;
    if (n >= ENC) return;
    const float* base = mbx + ((size_t)(b*TS + t)*SEQ)*ENC + n;
    float s = 0.f, ss = 0.f;
    for (int i = 0; i < SEQ; i++){
        float v = base[(size_t)i*ENC];
        s += v; ss += v*v;
    }
    float m = s * (1.f/SEQ);
    float var = ss * (1.f/SEQ) - m*m;
    g_mean[b*ENC + n] = m;
    g_std [b*ENC + n] = sqrtf(var + EPS);
}

// ---------------- build xin [B, NTOK, SEQ] ----------------
__global__ void xin_kernel(const float* __restrict__ mbx,
                           const float* __restrict__ mbxm, int t){
    size_t total = (size_t)B_*NTOK*SEQ;
    size_t idx = (size_t)blockIdx.x*blockDim.x + threadIdx.x;
    if (idx >= total) return;
    int s = (int)(idx % SEQ);
    size_t r = idx / SEQ;
    int n = (int)(r % NTOK);
    int b = (int)(r / NTOK);
    float v;
    if (n < ENC){
        v = mbx[((size_t)(b*TS + t)*SEQ + s)*ENC + n];
        v = (v - g_mean[b*ENC + n]) / g_std[b*ENC + n];
    } else {
        v = mbxm[((size_t)(b*TS + t)*SEQ + s)*MARKD + (n - ENC)];
    }
    g_xin[idx] = v;
}

// ---------------- GEMM: C = A @ W^T + bias (FFMA2, double-buffered) ------
struct GemmArgs {
    const float* A[3];
    const float* W[3];
    const float* Bv[3];
    float*       C[3];
};

template<int TM, int TN, int ACT>
__global__ __launch_bounds__(256)
void gemm2_kernel(GemmArgs p, int M, int N, int K,
                  int tilesM, int tilesN, int nTiles){
    constexpr int AV  = TM/64;      // float4 loads per thread for A tile
    constexpr int BV  = TN/64;
    constexpr int TMR = TM/16;      // rows per thread
    constexpr int TNR = TN/16;      // cols per thread

    __shared__ __align__(16) float              As[2][16][TM];
    __shared__ __align__(16) unsigned long long Bs[2][16][TN]; // (b,b) dup

    const int tid   = threadIdx.x;
    const int ldRow = tid >> 2;        // 0..63
    const int ldCol = (tid & 3) * 4;   // 0,4,8,12
    const int tr = tid >> 4, tc = tid & 15;
    const int tpz = tilesM * tilesN;

    for (int t = blockIdx.x; t < nTiles; t += gridDim.x){
        const int z  = t / tpz;
        const int r  = t - z*tpz;
        const int bm = (r / tilesN) * TM;
        const int bn = (r % tilesN) * TN;
        const float* __restrict__ A    = p.A[z];
        const float* __restrict__ W    = p.W[z];
        const float* __restrict__ bias = p.Bv[z];
        float*       __restrict__ C    = p.C[z];

        unsigned long long acc[TMR/2][TNR];
        #pragma unroll
        for (int i = 0; i < TMR/2; i++)
            #pragma unroll
            for (int j = 0; j < TNR; j++) acc[i][j] = 0ull;

        float4 Areg[AV], Breg[BV];
        // prologue: load k-tile 0
        #pragma unroll
        for (int v = 0; v < AV; v++){
            int gm = bm + ldRow + 64*v;
            Areg[v] = (gm < M) ? *(const float4*)(A + (size_t)gm*K + ldCol)
                               : make_float4(0.f,0.f,0.f,0.f);
        }
        #pragma unroll
        for (int v = 0; v < BV; v++){
            int gn = bn + ldRow + 64*v;
            Breg[v] = (gn < N) ? *(const float4*)(W + (size_t)gn*K + ldCol)
                               : make_float4(0.f,0.f,0.f,0.f);
        }
        #pragma unroll
        for (int v = 0; v < AV; v++){
            int row = ldRow + 64*v;
            As[0][ldCol+0][row] = Areg[v].x; As[0][ldCol+1][row] = Areg[v].y;
            As[0][ldCol+2][row] = Areg[v].z; As[0][ldCol+3][row] = Areg[v].w;
        }
        #pragma unroll
        for (int v = 0; v < BV; v++){
            int row = ldRow + 64*v;
            Bs[0][ldCol+0][row] = packdup(Breg[v].x);
            Bs[0][ldCol+1][row] = packdup(Breg[v].y);
            Bs[0][ldCol+2][row] = packdup(Breg[v].z);
            Bs[0][ldCol+3][row] = packdup(Breg[v].w);
        }
        __syncthreads();

        const int KT = K >> 4;
        int buf = 0;
        for (int kt = 0; kt < KT; kt++){
            if (kt + 1 < KT){
                const int k0 = (kt+1) << 4;
                #pragma unroll
                for (int v = 0; v < AV; v++){
                    int gm = bm + ldRow + 64*v;
                    Areg[v] = (gm < M) ? *(const float4*)(A + (size_t)gm*K + k0 + ldCol)
                                       : make_float4(0.f,0.f,0.f,0.f);
                }
                #pragma unroll
                for (int v = 0; v < BV; v++){
                    int gn = bn + ldRow + 64*v;
                    Breg[v] = (gn < N) ? *(const float4*)(W + (size_t)gn*K + k0 + ldCol)
                                       : make_float4(0.f,0.f,0.f,0.f);
                }
            }
            #pragma unroll
            for (int kk = 0; kk < 16; kk++){
                const ulonglong2* pa = reinterpret_cast<const ulonglong2*>(&As[buf][kk][tr*TMR]);
                const ulonglong2* pb = reinterpret_cast<const ulonglong2*>(&Bs[buf][kk][tc*TNR]);
                unsigned long long ar[TMR/2], br[TNR];
                #pragma unroll
                for (int v = 0; v < TMR/4; v++){
                    ulonglong2 q = pa[v];
                    ar[2*v] = q.x; ar[2*v+1] = q.y;
                }
                #pragma unroll
                for (int v = 0; v < TNR/2; v++){
                    ulonglong2 q = pb[v];
                    br[2*v] = q.x; br[2*v+1] = q.y;
                }
                #pragma unroll
                for (int i = 0; i < TMR/2; i++)
                    #pragma unroll
                    for (int j = 0; j < TNR; j++)
                        acc[i][j] = ffma2(ar[i], br[j], acc[i][j]);
            }
            if (kt + 1 < KT){
                int nb = buf ^ 1;
                #pragma unroll
                for (int v = 0; v < AV; v++){
                    int row = ldRow + 64*v;
                    As[nb][ldCol+0][row] = Areg[v].x; As[nb][ldCol+1][row] = Areg[v].y;
                    As[nb][ldCol+2][row] = Areg[v].z; As[nb][ldCol+3][row] = Areg[v].w;
                }
                #pragma unroll
                for (int v = 0; v < BV; v++){
                    int row = ldRow + 64*v;
                    Bs[nb][ldCol+0][row] = packdup(Breg[v].x);
                    Bs[nb][ldCol+1][row] = packdup(Breg[v].y);
                    Bs[nb][ldCol+2][row] = packdup(Breg[v].z);
                    Bs[nb][ldCol+3][row] = packdup(Breg[v].w);
                }
                __syncthreads();
                buf ^= 1;
            }
        }

        #pragma unroll
        for (int i = 0; i < TMR/2; i++){
            int gm0 = bm + tr*TMR + 2*i;
            #pragma unroll
            for (int j = 0; j < TNR; j++){
                int col = bn + tc*TNR + j;
                if (col >= N) continue;
                float2 v = unpack2(acc[i][j]);
                float bs = bias[col];
                float c0 = v.x + bs, c1 = v.y + bs;
                if (ACT == 1){
                    c0 = 0.5f*c0*(1.f + erff(c0*0.70710678118654752f));
                    c1 = 0.5f*c1*(1.f + erff(c1*0.70710678118654752f));
                }
                if (gm0     < M) C[(size_t)gm0    *N + col] = c0;
                if (gm0 + 1 < M) C[(size_t)(gm0+1)*N + col] = c1;
            }
        }
        __syncthreads();
    }
}

// ---------------- attention: scores = scale * Q K^T (f32x2 k-packing) ----
__global__ __launch_bounds__(256) void scores_kernel(){
    const int bh = blockIdx.z;
    const int b = bh >> 3, h = bh & 7;
    const int i0 = blockIdx.y * 64, j0 = blockIdx.x * 64;
    __shared__ __align__(16) float Qs[64][36];
    __shared__ __align__(16) float Ks[64][36];
    const float* q = g_qkv + ((size_t)b*NTOK)*D + h*EH;
    const float* k = g_qkv + (size_t)MROWS*D + ((size_t)b*NTOK)*D + h*EH;

    for (int idx = threadIdx.x; idx < 64*32; idx += 256){
        int r = idx >> 5, e = idx & 31;
        int gi = i0 + r, gj = j0 + r;
        Qs[r][e] = (gi < NTOK) ? q[(size_t)gi*D + e] : 0.f;
        Ks[r][e] = (gj < NTOK) ? k[(size_t)gj*D + e] : 0.f;
    }
    __syncthreads();

    const int tr = threadIdx.x & 15, tc = threadIdx.x >> 4;
    unsigned long long acc[4][4];
    #pragma unroll
    for (int i = 0; i < 4; i++)
        #pragma unroll
        for (int j = 0; j < 4; j++) acc[i][j] = 0ull;

    #pragma unroll
    for (int ee = 0; ee < 32; ee += 4){
        ulonglong2 qa[4], kb[4];
        #pragma unroll
        for (int i = 0; i < 4; i++)
            qa[i] = *reinterpret_cast<const ulonglong2*>(&Qs[tr + 16*i][ee]);
        #pragma unroll
        for (int j = 0; j < 4; j++)
            kb[j] = *reinterpret_cast<const ulonglong2*>(&Ks[tc*4 + j][ee]);
        #pragma unroll
        for (int i = 0; i < 4; i++)
            #pragma unroll
            for (int j = 0; j < 4; j++){
                acc[i][j] = ffma2(qa[i].x, kb[j].x, acc[i][j]);
                acc[i][j] = ffma2(qa[i].y, kb[j].y, acc[i][j]);
            }
    }

    float* S = g_scores + (size_t)bh*NTOK*NTOK;
    const float scale = 0.17677669529663688f;  // 1/sqrt(32)
    #pragma unroll
    for (int i = 0; i < 4; i++){
        int gi = i0 + tr + 16*i;
        if (gi >= NTOK) continue;
        #pragma unroll
        for (int j = 0; j < 4; j++){
            int gj = j0 + tc*4 + j;
            if (gj < NTOK){
                float2 v = unpack2(acc[i][j]);
                S[(size_t)gi*NTOK + gj] = (v.x + v.y)*scale;
            }
        }
    }
}

// ---------------- softmax over last dim (rows of 866) ----------------
__global__ __launch_bounds__(128) void softmax_kernel(){
    size_t row = blockIdx.x;
    float* p = g_scores + row*(size_t)NTOK;
    float v[7];
    float mx = -1e30f;
    #pragma unroll
    for (int i = 0; i < 7; i++){
        int j = threadIdx.x + i*128;
        v[i] = (j < NTOK) ? p[j] : -1e30f;
        mx = fmaxf(mx, v[i]);
    }
    mx = blockReduce(mx, true);
    float sum = 0.f;
    #pragma unroll
    for (int i = 0; i < 7; i++){
        v[i] = expf(v[i] - mx);
        sum += v[i];
    }
    sum = blockReduce(sum, false);
    float inv = 1.f / sum;
    #pragma unroll
    for (int i = 0; i < 7; i++){
        int j = threadIdx.x + i*128;
        if (j < NTOK) p[j] = v[i]*inv;
    }
}

// ---------------- att = P @ V (f32x2 j-packing) ----------------
__global__ __launch_bounds__(256) void av_kernel(){
    const int bh = blockIdx.y;
    const int b = bh >> 3, h = bh & 7;
    const int i0 = blockIdx.x * 64;
    __shared__ __align__(16) float Ps [64][68];
    __shared__ __align__(16) float VsT[32][68];
    const float* S = g_scores + (size_t)bh*NTOK*NTOK;
    const float* v = g_qkv + 2*(size_t)MROWS*D + ((size_t)b*NTOK)*D + h*EH;
    const int tr = threadIdx.x & 15, tc = threadIdx.x >> 4;

    unsigned long long acc[4][2];
    #pragma unroll
    for (int i = 0; i < 4; i++){ acc[i][0] = 0ull; acc[i][1] = 0ull; }

    for (int j0 = 0; j0 < NTOK; j0 += 64){
        __syncthreads();
        for (int idx = threadIdx.x; idx < 64*64; idx += 256){
            int li = idx >> 6, lj = idx & 63;
            int gi = i0 + li, gj = j0 + lj;
            Ps[li][lj] = (gi < NTOK && gj < NTOK) ? S[(size_t)gi*NTOK + gj] : 0.f;
        }
        for (int idx = threadIdx.x; idx < 64*32; idx += 256){
            int lj = idx >> 5, e = idx & 31;
            int gj = j0 + lj;
            VsT[e][lj] = (gj < NTOK) ? v[(size_t)gj*D + e] : 0.f;
        }
        __syncthreads();
        #pragma unroll
        for (int jj = 0; jj < 64; jj += 4){
            ulonglong2 pa[4], vb[2];
            #pragma unroll
            for (int i = 0; i < 4; i++)
                pa[i] = *reinterpret_cast<const ulonglong2*>(&Ps[tr + 16*i][jj]);
            #pragma unroll
            for (int c = 0; c < 2; c++)
                vb[c] = *reinterpret_cast<const ulonglong2*>(&VsT[tc*2 + c][jj]);
            #pragma unroll
            for (int i = 0; i < 4; i++)
                #pragma unroll
                for (int c = 0; c < 2; c++){
                    acc[i][c] = ffma2(pa[i].x, vb[c].x, acc[i][c]);
                    acc[i][c] = ffma2(pa[i].y, vb[c].y, acc[i][c]);
                }
        }
    }
    #pragma unroll
    for (int i = 0; i < 4; i++){
        int gi = i0 + tr + 16*i;
        if (gi >= NTOK) continue;
        #pragma unroll
        for (int c = 0; c < 2; c++){
            float2 u = unpack2(acc[i][c]);
            g_att[((size_t)b*NTOK + gi)*D + h*EH + tc*2 + c] = u.x + u.y;
        }
    }
}

// ---------------- LayerNorm(x [- sub]) over D=256 ----------------
__global__ __launch_bounds__(256) void ln_kernel(const float* __restrict__ X,
                                                 const float* __restrict__ Sub,
                                                 const float* __restrict__ g,
                                                 const float* __restrict__ beta,
                                                 float* __restrict__ Out){
    int row = blockIdx.x, d = threadIdx.x;
    size_t i = (size_t)row*D + d;
    float v = X[i] - (Sub ? Sub[i] : 0.f);
    float mean = blockReduce(v, false) * (1.f/D);
    float dv = v - mean;
    float var = blockReduce(dv*dv, false) * (1.f/D);
    Out[i] = dv * rsqrtf(var + EPS) * g[d] + beta[d];
}

// ---------------- elementwise fusion kernels ----------------
__global__ void sub_kernel(const float* __restrict__ a, const float* __restrict__ b,
                           float* __restrict__ c, size_t n){
    size_t i = (size_t)blockIdx.x*blockDim.x + threadIdx.x;
    if (i < n) c[i] = a[i] - b[i];
}

__global__ void glu_kernel(const float* __restrict__ a, const float* __restrict__ b,
                           float* __restrict__ c, size_t n){
    size_t i = (size_t)blockIdx.x*blockDim.x + threadIdx.x;
    if (i < n) c[i] = (1.f/(1.f + expf(-a[i]))) * b[i];
}

__global__ void cat_kernel(const float* __restrict__ xatt, const float* __restrict__ y){
    size_t n = (size_t)MROWS*2*D;
    size_t i = (size_t)blockIdx.x*blockDim.x + threadIdx.x;
    if (i >= n) return;
    int c = (int)(i % (2*D));
    size_t r = i / (2*D);
    g_cat[i] = (c < D) ? xatt[r*D + c] : y[r*D + c - D];
}

__global__ void outcomb_kernel(int l){
    size_t n = (size_t)MROWS*DB;
    size_t i = (size_t)blockIdx.x*blockDim.x + threadIdx.x;
    if (i >= n) return;
    float a = g_o56[i], b = g_o56[n + i];
    float v = (1.f/(1.f + expf(-a))) * b;
    g_out[i] = l ? (v - g_out[i]) : v;
}

// ---------------- final: de-standardize, transpose, 2-scale mean ----------
__global__ void final_kernel(float* __restrict__ out, int t){
    size_t total = (size_t)B_*DB*ENC;
    size_t idx = (size_t)blockIdx.x*blockDim.x + threadIdx.x;
    if (idx >= total) return;
    int n = (int)(idx % ENC);
    size_t r = idx / ENC;
    int p = (int)(r % DB);
    int b = (int)(r / DB);
    float v = g_out[((size_t)b*NTOK + n)*DB + p] * g_std[b*ENC + n] + g_mean[b*ENC + n];
    v *= 0.5f;
    if (t == 0) out[idx] = v; else out[idx] += v;
}

// ---------------- host ----------------
static inline GemmArgs ga1(const float* A, const float* W, const float* b, float* C){
    GemmArgs g = {};
    g.A[0] = A; g.W[0] = W; g.Bv[0] = b; g.C[0] = C;
    return g;
}
static inline int gsz(int nt){ return nt < 592 ? nt : 592; }

extern "C" void kernel_launch(void* const* d_in, const int* in_sizes, int n_in,
                              void* d_out, int out_size){
    const float* mbx  = (const float*)d_in[0];
    const float* mbxm = (const float*)d_in[1];
    const float* embW = (const float*)d_in[4];
    const float* embB = (const float*)d_in[5];
    const float* Wq = (const float*)d_in[6];
    const float* Wk = (const float*)d_in[7];
    const float* Wv = (const float*)d_in[8];
    const float* Wo = (const float*)d_in[9];
    const float* W3 = (const float*)d_in[10];
    const float* W4 = (const float*)d_in[11];
    const float* bq = (const float*)d_in[12];
    const float* bk = (const float*)d_in[13];
    const float* bv = (const float*)d_in[14];
    const float* bo = (const float*)d_in[15];
    const float* b3 = (const float*)d_in[16];
    const float* b4 = (const float*)d_in[17];
    const float* W1 = (const float*)d_in[18];
    const float* b1 = (const float*)d_in[19];
    const float* W2 = (const float*)d_in[20];
    const float* b2 = (const float*)d_in[21];
    const float* W5 = (const float*)d_in[22];
    const float* b5 = (const float*)d_in[23];
    const float* W6 = (const float*)d_in[24];
    const float* b6 = (const float*)d_in[25];
    const float* ln1g = (const float*)d_in[26];
    const float* ln1b = (const float*)d_in[27];
    const float* ln2g = (const float*)d_in[28];
    const float* ln2b = (const float*)d_in[29];
    float* out = (float*)d_out;

    float *xin, *h, *qkv, *att, *xatt, *xln, *y1, *y, *xs, *hh, *cat, *o56;
    cudaGetSymbolAddress((void**)&xin,  g_xin);
    cudaGetSymbolAddress((void**)&h,    g_h);
    cudaGetSymbolAddress((void**)&qkv,  g_qkv);
    cudaGetSymbolAddress((void**)&att,  g_att);
    cudaGetSymbolAddress((void**)&xatt, g_xatt);
    cudaGetSymbolAddress((void**)&xln,  g_xln);
    cudaGetSymbolAddress((void**)&y1,   g_y1);
    cudaGetSymbolAddress((void**)&y,    g_y);
    cudaGetSymbolAddress((void**)&xs,   g_xs);
    cudaGetSymbolAddress((void**)&hh,   g_hh);
    cudaGetSymbolAddress((void**)&cat,  g_cat);
    cudaGetSymbolAddress((void**)&o56,  g_o56);

    const size_t MD = (size_t)MROWS*D;
    const int tm128 = 55;   // ceil(6928/128)
    const int tm64  = 109;  // ceil(6928/64)

    for (int t = 0; t < TS; t++){
        stats_kernel<<<dim3((ENC + 255)/256, B_), 256>>>(mbx, t);
        {
            size_t n = (size_t)B_*NTOK*SEQ;
            xin_kernel<<<(unsigned)((n + 255)/256), 256>>>(mbx, mbxm, t);
        }
        // embed: M=6928, N=256, K=720
        gemm2_kernel<64,64,0><<<gsz(tm64*4), 256>>>(
            ga1(xin, embW, embB, h), MROWS, D, SEQ, tm64, 4, tm64*4);

        for (int l = 0; l < LAYERS; l++){
            // Q, K, V in one launch
            GemmArgs q3 = {};
            q3.A[0] = h; q3.A[1] = h; q3.A[2] = h;
            q3.W[0] = Wq + (size_t)l*D*D; q3.W[1] = Wk + (size_t)l*D*D; q3.W[2] = Wv + (size_t)l*D*D;
            q3.Bv[0] = bq + l*D; q3.Bv[1] = bk + l*D; q3.Bv[2] = bv + l*D;
            q3.C[0] = qkv; q3.C[1] = qkv + MD; q3.C[2] = qkv + 2*MD;
            gemm2_kernel<128,64,0><<<gsz(tm128*4*3), 256>>>(q3, MROWS, D, D,
                                                            tm128, 4, tm128*4*3);

            scores_kernel<<<dim3(14, 14, B_*NH), 256>>>();
            softmax_kernel<<<B_*NH*NTOK, 128>>>();
            av_kernel<<<dim3(14, B_*NH), 256>>>();

            gemm2_kernel<64,64,0><<<gsz(tm64*4), 256>>>(
                ga1(att, Wo + (size_t)l*D*D, bo + l*D, xatt), MROWS, D, D,
                tm64, 4, tm64*4);

            ln_kernel<<<MROWS, 256>>>(h, xatt, ln1g + l*D, ln1b + l*D, xln);

            gemm2_kernel<128,64,1><<<gsz(tm128*8), 256>>>(
                ga1(xln, W1 + (size_t)l*DFF*D, b1 + l*DFF, y1), MROWS, DFF, D,
                tm128, 8, tm128*8);
            gemm2_kernel<64,64,0><<<gsz(tm64*4), 256>>>(
                ga1(y1, W2 + (size_t)l*D*DFF, b2 + l*D, y), MROWS, D, DFF,
                tm64, 4, tm64*4);

            sub_kernel<<<(unsigned)((MD + 255)/256), 256>>>(xln, y, xs, MD);

            GemmArgs g34 = {};
            g34.A[0] = xs; g34.A[1] = xs;
            g34.W[0] = W3 + (size_t)l*D*D; g34.W[1] = W4 + (size_t)l*D*D;
            g34.Bv[0] = b3 + l*D; g34.Bv[1] = b4 + l*D;
            g34.C[0] = qkv; g34.C[1] = qkv + MD;   // reuse q/k slots
            gemm2_kernel<128,64,0><<<gsz(tm128*4*2), 256>>>(g34, MROWS, D, D,
                                                            tm128, 4, tm128*4*2);

            glu_kernel<<<(unsigned)((MD + 255)/256), 256>>>(qkv, qkv + MD, hh, MD);
            cat_kernel<<<(unsigned)(((size_t)MROWS*2*D + 255)/256), 256>>>(xatt, y);

            GemmArgs g56 = {};
            g56.A[0] = cat; g56.A[1] = cat;
            g56.W[0] = W5 + (size_t)l*DB*2*D; g56.W[1] = W6 + (size_t)l*DB*2*D;
            g56.Bv[0] = b5 + l*DB; g56.Bv[1] = b6 + l*DB;
            g56.C[0] = o56; g56.C[1] = o56 + (size_t)MROWS*DB;
            gemm2_kernel<128,64,0><<<gsz(tm128*12*2), 256>>>(g56, MROWS, DB, 2*D,
                                                             tm128, 12, tm128*12*2);

            outcomb_kernel<<<(unsigned)(((size_t)MROWS*DB + 255)/256), 256>>>(l);

            ln_kernel<<<MROWS, 256>>>(hh, (const float*)nullptr, ln2g + l*D, ln2b + l*D, h);
        }

        final_kernel<<<(unsigned)(((size_t)B_*DB*ENC + 255)/256), 256>>>(out, t);
    }
}